// round 11
// baseline (speedup 1.0000x reference)
#include <cuda_runtime.h>
#include <cuda_fp16.h>
#include <cstdint>

// ============================================================================
// QuantizedLoRALinear on GB300 (sm_103 PTX target -> no tcgen05; HMMA path).
//
//   out[8192,4096] = ws * ( x[8192,4096] @ Wq[4096,4096]^T )
//                  + 2*(x @ A^T)[8192,16] @ B[4096,16]^T
//
// R11: same single-pass fp16 scheme as R10 (Wq exact in fp16, x -> fp16 raw,
//   fp32 acc, ws + LoRA in epilogue), but 512 threads (4 warps/SMSP) to hide
//   ldsm/barrier bubbles: warp tile 32x64, 16 warps (4M x 4N).
//   k_pad_b fused into k_lora_t; k_gemm is the 4th launch (ncu capture slot).
//
// GEMM: CTA tile 128x256, BK=64 fp16 (128B rows, SW128), 4-stage cp.async.
// ============================================================================

#define MDIM 8192
#define NDIM 4096
#define KDIM 4096

#define TBM 128
#define TBN 256
#define TBK 64
#define NKC (KDIM / TBK)   // 64 chunks

#define STAGE_BYTES 49152  // A 16K | B 32K
#define OFF_A 0
#define OFF_B 16384
#define NSTAGE 4
#define SMEM_ALLOC (NSTAGE * STAGE_BYTES + 1024)

// ---------------- scratch (__device__ globals; no allocations) --------------
__device__ __half g_xh [(size_t)MDIM * KDIM];  // 64 MB fp16(x)
__device__ __half g_wh [(size_t)NDIM * KDIM];  // 32 MB fp16(Wq), exact
__device__ __half g_t2a[(size_t)MDIM * 64];    // fp16(2*x@A^T), cols>=16 zero
__device__ __half g_bb [(size_t)NDIM * 64];    // fp16(lora_B),  cols>=16 zero

// ---------------- PTX helpers ----------------------------------------------
__device__ __forceinline__ uint32_t smem_u32(const void* p) {
    uint32_t a;
    asm("{ .reg .u64 t; cvta.to.shared.u64 t, %1; cvt.u32.u64 %0, t; }"
        : "=r"(a) : "l"(p));
    return a;
}

#define SWZ128(off) ((off) ^ (((off) >> 3) & 0x70))

__device__ __forceinline__ void cpa16(uint32_t dst, const void* src) {
    asm volatile("cp.async.cg.shared.global [%0], [%1], 16;\n" :: "r"(dst), "l"(src));
}
__device__ __forceinline__ void cpa_commit() {
    asm volatile("cp.async.commit_group;\n" ::: "memory");
}
template <int N> __device__ __forceinline__ void cpa_wait() {
    asm volatile("cp.async.wait_group %0;\n" :: "n"(N) : "memory");
}

__device__ __forceinline__ void ldsm_x4(uint32_t* r, uint32_t addr) {
    asm volatile("ldmatrix.sync.aligned.m8n8.x4.shared.b16 {%0,%1,%2,%3}, [%4];"
                 : "=r"(r[0]), "=r"(r[1]), "=r"(r[2]), "=r"(r[3]) : "r"(addr));
}

__device__ __forceinline__ void mma16816(float* c, const uint32_t* a,
                                         uint32_t b0, uint32_t b1) {
    asm volatile(
        "mma.sync.aligned.m16n8k16.row.col.f32.f16.f16.f32 "
        "{%0,%1,%2,%3}, {%4,%5,%6,%7}, {%8,%9}, {%0,%1,%2,%3};"
        : "+f"(c[0]), "+f"(c[1]), "+f"(c[2]), "+f"(c[3])
        : "r"(a[0]), "r"(a[1]), "r"(a[2]), "r"(a[3]), "r"(b0), "r"(b1));
}

// ---------------- prep kernels ----------------------------------------------

// W int32 -> fp16 (exact). 4 elems/thread.
__global__ void k_convert_w(const int* __restrict__ w) {
    size_t i = ((size_t)blockIdx.x * blockDim.x + threadIdx.x) * 4;
    int4 v = *reinterpret_cast<const int4*>(w + i);
    __half2* dst = reinterpret_cast<__half2*>(g_wh + i);
    dst[0] = __halves2half2(__float2half_rn((float)v.x), __float2half_rn((float)v.y));
    dst[1] = __halves2half2(__float2half_rn((float)v.z), __float2half_rn((float)v.w));
}

// x fp32 -> fp16 raw. 4 elems/thread.
__global__ void k_convert_x(const float* __restrict__ x) {
    size_t i = ((size_t)blockIdx.x * blockDim.x + threadIdx.x) * 4;
    float4 v = *reinterpret_cast<const float4*>(x + i);
    __half2* dst = reinterpret_cast<__half2*>(g_xh + i);
    dst[0] = __halves2half2(__float2half_rn(v.x), __float2half_rn(v.y));
    dst[1] = __halves2half2(__float2half_rn(v.z), __float2half_rn(v.w));
}

// t2a[m][r] = fp16(2 * sum_k x[m][k]*A[r][k]) for r<16, 0 for r in [16,64),
// PLUS fused bb[n][r] = fp16(B[n][r]) padding (256 elems per block).
__global__ __launch_bounds__(256) void k_lora_t(const float* __restrict__ x,
                                                const float* __restrict__ A,
                                                const float* __restrict__ B) {
    __shared__ float sA[16 * 512];
    __shared__ float sT[8][16];
    const int tid = threadIdx.x;
    const int w = tid >> 5, l = tid & 31;
    const int m = blockIdx.x * 8 + w;

    // fused bb fill: 1024 blocks x 256 threads covers 4096*64
    {
        int i = blockIdx.x * 256 + tid;
        int n = i >> 6, r = i & 63;
        float v = (r < 16) ? B[n * 16 + r] : 0.f;
        g_bb[i] = __float2half_rn(v);
    }

    float acc[16];
#pragma unroll
    for (int r = 0; r < 16; r++) acc[r] = 0.f;

    for (int kc = 0; kc < 8; kc++) {
        __syncthreads();
#pragma unroll
        for (int i = 0; i < 8; i++) {
            int v = tid + 256 * i;
            int r = v >> 7, c4 = v & 127;
            *reinterpret_cast<float4*>(&sA[r * 512 + c4 * 4]) =
                *reinterpret_cast<const float4*>(A + (size_t)r * KDIM + kc * 512 + c4 * 4);
        }
        __syncthreads();
#pragma unroll
        for (int i = 0; i < 16; i++) {
            int k = l + i * 32;
            float xv = x[(size_t)m * KDIM + kc * 512 + k];
#pragma unroll
            for (int r = 0; r < 16; r++) acc[r] += xv * sA[r * 512 + k];
        }
    }
#pragma unroll
    for (int r = 0; r < 16; r++) {
        float v = acc[r];
#pragma unroll
        for (int off = 16; off; off >>= 1) v += __shfl_xor_sync(0xffffffffu, v, off);
        acc[r] = v;
    }
    if (l == 0) {
#pragma unroll
        for (int r = 0; r < 16; r++) sT[w][r] = acc[r];
    }
    __syncwarp();
    float tv = (l < 16) ? sT[w][l] : 0.f;
    g_t2a[(size_t)m * 64 + l]      = __float2half_rn(2.0f * tv);
    g_t2a[(size_t)m * 64 + 32 + l] = __float2half_rn(0.f);
}

// ---------------- main HMMA GEMM ---------------------------------------------

__global__ __launch_bounds__(512, 1) void k_gemm(float* __restrict__ out,
                                                 const float* __restrict__ wsp) {
    extern __shared__ char smem_raw[];
    const uint32_t sb = (smem_u32(smem_raw) + 1023u) & ~1023u;  // 1024-aligned
    const int tid = threadIdx.x;
    const int wid = tid >> 5;
    const int lid = tid & 31;
    const int wm = wid & 3;    // 4 warps along M (32 rows each)
    const int wn = wid >> 2;   // 4 warps along N (64 cols each)

    // 8-wide M supertiles for L2 locality: 128 bids per group = 8 M x 16 N.
    const int bid = blockIdx.x;
    const int grp = bid >> 7, loc = bid & 127;
    const int m0 = (grp * 8 + (loc & 7)) * TBM;
    const int n0 = (loc >> 3) * TBN;

    const float ws = wsp[0];

    float acc[2][8][4];
#pragma unroll
    for (int i = 0; i < 2; i++)
#pragma unroll
        for (int j = 0; j < 8; j++)
#pragma unroll
            for (int t = 0; t < 4; t++) acc[i][j][t] = 0.f;

    // cooperative swizzled loader for K-chunk k into its stage slot (512 thr)
    auto load_chunk = [&](int k) {
        const uint32_t slot = sb + (uint32_t)(k % NSTAGE) * STAGE_BYTES;
        const __half* srcA = g_xh + (size_t)m0 * KDIM + (size_t)k * TBK;
        const __half* srcB = g_wh + (size_t)n0 * KDIM + (size_t)k * TBK;
#pragma unroll
        for (int i = 0; i < 2; i++) {                   // A tile: 1024 x 16B
            int c = tid + 512 * i;
            int row = c >> 3, c16 = c & 7;
            uint32_t so = SWZ128((uint32_t)(row * 128 + c16 * 16));
            cpa16(slot + OFF_A + so, srcA + (size_t)row * KDIM + c16 * 8);
        }
#pragma unroll
        for (int i = 0; i < 4; i++) {                   // B tile: 2048 x 16B
            int c = tid + 512 * i;
            int row = c >> 3, c16 = c & 7;
            uint32_t so = SWZ128((uint32_t)(row * 128 + c16 * 16));
            cpa16(slot + OFF_B + so, srcB + (size_t)row * KDIM + c16 * 8);
        }
    };

    load_chunk(0); cpa_commit();
    load_chunk(1); cpa_commit();
    load_chunk(2); cpa_commit();

    // per-lane ldmatrix addressing constants
    const uint32_t lrow = (uint32_t)(lid & 15);        // row within 16-row tile
    const uint32_t lcol = (uint32_t)((lid >> 4) * 16); // 0 or 16 bytes (k half)
    const uint32_t swz  = ((lrow & 7u) << 4);

    for (int k = 0; k < NKC; k++) {
        if (k + 3 < NKC) load_chunk(k + 3);
        cpa_commit();                      // keep group count uniform
        cpa_wait<3>();                     // stage k resident (this thread)
        __syncthreads();                   // publish to all threads

        const uint32_t slot = sb + (uint32_t)(k % NSTAGE) * STAGE_BYTES;
        const uint32_t aBase = slot + OFF_A + (uint32_t)(wm * 32) * 128 + lrow * 128;
        const uint32_t bBase = slot + OFF_B + (uint32_t)(wn * 64) * 128 + lrow * 128;

#pragma unroll
        for (int ks = 0; ks < 4; ks++) {
            const uint32_t csw = ((uint32_t)(ks * 32) + lcol) ^ swz;

            uint32_t bfr[4][4];
#pragma unroll
            for (int ntp = 0; ntp < 4; ntp++)
                ldsm_x4(bfr[ntp], bBase + (uint32_t)(ntp * 16) * 128 + csw);

            uint32_t af[2][4];
#pragma unroll
            for (int mt = 0; mt < 2; mt++)
                ldsm_x4(af[mt], aBase + (uint32_t)(mt * 16) * 128 + csw);
#pragma unroll
            for (int mt = 0; mt < 2; mt++)
#pragma unroll
                for (int nt = 0; nt < 8; nt++)
                    mma16816(acc[mt][nt], af[mt],
                             bfr[nt >> 1][nt & 1], bfr[nt >> 1][2 + (nt & 1)]);
        }
        __syncthreads();                   // done reading slot before overwrite
    }

    // ---------- epilogue: scale by ws, add LoRA via one fp16 MMA chunk -------
    {
        const char* tA = reinterpret_cast<const char*>(g_t2a) + (size_t)m0 * 128;
        const char* tB = reinterpret_cast<const char*>(g_bb)  + (size_t)n0 * 128;
#pragma unroll
        for (int i = 0; i < 2; i++) {      // A': 1024 segs
            int c = tid + 512 * i;
            int row = c >> 3, c16 = c & 7;
            uint32_t so = SWZ128((uint32_t)(row * 128 + c16 * 16));
            cpa16(sb + OFF_A + so, tA + (size_t)row * 128 + c16 * 16);
        }
#pragma unroll
        for (int i = 0; i < 4; i++) {      // B': 2048 segs
            int c = tid + 512 * i;
            int row = c >> 3, c16 = c & 7;
            uint32_t so = SWZ128((uint32_t)(row * 128 + c16 * 16));
            cpa16(sb + OFF_B + so, tB + (size_t)row * 128 + c16 * 16);
        }
        cpa_commit();
        cpa_wait<0>();
        __syncthreads();
    }

    // scale base accumulators
#pragma unroll
    for (int mt = 0; mt < 2; mt++)
#pragma unroll
        for (int nt = 0; nt < 8; nt++)
#pragma unroll
            for (int e = 0; e < 4; e++) acc[mt][nt][e] *= ws;

    // LoRA fp16 MMA (ks=0 slice carries the 16 real rank columns; rest zero)
    {
        const uint32_t csw0 = lcol ^ swz;
        const uint32_t aB = sb + OFF_A + (uint32_t)(wm * 32) * 128 + lrow * 128;
        const uint32_t bB = sb + OFF_B + (uint32_t)(wn * 64) * 128 + lrow * 128;
        uint32_t bl[4][4];
#pragma unroll
        for (int ntp = 0; ntp < 4; ntp++)
            ldsm_x4(bl[ntp], bB + (uint32_t)(ntp * 16) * 128 + csw0);
        uint32_t al[2][4];
#pragma unroll
        for (int mt = 0; mt < 2; mt++)
            ldsm_x4(al[mt], aB + (uint32_t)(mt * 16) * 128 + csw0);
#pragma unroll
        for (int mt = 0; mt < 2; mt++)
#pragma unroll
            for (int nt = 0; nt < 8; nt++)
                mma16816(acc[mt][nt], al[mt],
                         bl[nt >> 1][nt & 1], bl[nt >> 1][2 + (nt & 1)]);
    }

    // store (float2 per lane, 32B-sector aligned)
    const int rBase = m0 + wm * 32 + (lid >> 2);
    const int cBase = n0 + wn * 64 + (lid & 3) * 2;
#pragma unroll
    for (int mt = 0; mt < 2; mt++) {
#pragma unroll
        for (int nt = 0; nt < 8; nt++) {
            float* p0 = out + (size_t)(rBase + mt * 16) * NDIM + cBase + nt * 8;
            float* p1 = out + (size_t)(rBase + mt * 16 + 8) * NDIM + cBase + nt * 8;
            *reinterpret_cast<float2*>(p0) = make_float2(acc[mt][nt][0], acc[mt][nt][1]);
            *reinterpret_cast<float2*>(p1) = make_float2(acc[mt][nt][2], acc[mt][nt][3]);
        }
    }
}

// ---------------- launch -----------------------------------------------------

extern "C" void kernel_launch(void* const* d_in, const int* in_sizes, int n_in,
                              void* d_out, int out_size) {
    (void)in_sizes; (void)n_in; (void)out_size;
    const float* x  = (const float*)d_in[0];
    const int*   wi = (const int*)d_in[1];
    const float* ws = (const float*)d_in[2];
    const float* lA = (const float*)d_in[3];
    const float* lB = (const float*)d_in[4];
    float* out = (float*)d_out;

    cudaFuncSetAttribute(k_gemm, cudaFuncAttributeMaxDynamicSharedMemorySize, SMEM_ALLOC);

    k_convert_w<<<(NDIM * (size_t)KDIM) / (256 * 4), 256>>>(wi);
    k_convert_x<<<(MDIM * (size_t)KDIM) / (256 * 4), 256>>>(x);
    k_lora_t   <<<MDIM / 8, 256>>>(x, lA, lB);          // bb fill fused in
    k_gemm     <<<(MDIM / TBM) * (NDIM / TBN), 512, SMEM_ALLOC>>>(out, ws);
}

// round 13
// speedup vs baseline: 1.0821x; 1.0821x over previous
#include <cuda_runtime.h>
#include <cuda_fp16.h>
#include <cstdint>

// ============================================================================
// QuantizedLoRALinear on GB300 (sm_103 PTX target -> no tcgen05; HMMA path).
//
//   out[8192,4096] = ws * ( x[8192,4096] @ Wq[4096,4096]^T )
//                  + 2*(x @ A^T)[8192,16] @ B[4096,16]^T
//
// R12: single-pass fp16 scheme (Wq exact in fp16, x -> fp16 raw, fp32 acc,
//   ws + LoRA fp16-MMA in epilogue) on a 2-CTA/SM layout:
//   CTA tile 128x128, 256 threads (8 warps, 4M x 2N, warp tile 32x64),
//   3-stage cp.async (32 KB/stage, 96 KB/CTA) -> 2 CTAs resident per SM so
//   barrier/ldsm phases of one CTA are covered by the other CTA's MMAs.
// ============================================================================

#define MDIM 8192
#define NDIM 4096
#define KDIM 4096

#define TBM 128
#define TBN 128
#define TBK 64
#define NKC (KDIM / TBK)   // 64 chunks

#define STAGE_BYTES 32768  // A 16K | B 16K
#define OFF_A 0
#define OFF_B 16384
#define NSTAGE 3
#define SMEM_ALLOC (NSTAGE * STAGE_BYTES + 1024)   // 99328 B/CTA

// ---------------- scratch (__device__ globals; no allocations) --------------
__device__ __half g_xh [(size_t)MDIM * KDIM];  // 64 MB fp16(x)
__device__ __half g_wh [(size_t)NDIM * KDIM];  // 32 MB fp16(Wq), exact
__device__ __half g_t2a[(size_t)MDIM * 64];    // fp16(2*x@A^T), cols>=16 zero
__device__ __half g_bb [(size_t)NDIM * 64];    // fp16(lora_B),  cols>=16 zero

// ---------------- PTX helpers ----------------------------------------------
__device__ __forceinline__ uint32_t smem_u32(const void* p) {
    uint32_t a;
    asm("{ .reg .u64 t; cvta.to.shared.u64 t, %1; cvt.u32.u64 %0, t; }"
        : "=r"(a) : "l"(p));
    return a;
}

#define SWZ128(off) ((off) ^ (((off) >> 3) & 0x70))

__device__ __forceinline__ void cpa16(uint32_t dst, const void* src) {
    asm volatile("cp.async.cg.shared.global [%0], [%1], 16;\n" :: "r"(dst), "l"(src));
}
__device__ __forceinline__ void cpa_commit() {
    asm volatile("cp.async.commit_group;\n" ::: "memory");
}
template <int N> __device__ __forceinline__ void cpa_wait() {
    asm volatile("cp.async.wait_group %0;\n" :: "n"(N) : "memory");
}

__device__ __forceinline__ void ldsm_x4(uint32_t* r, uint32_t addr) {
    asm volatile("ldmatrix.sync.aligned.m8n8.x4.shared.b16 {%0,%1,%2,%3}, [%4];"
                 : "=r"(r[0]), "=r"(r[1]), "=r"(r[2]), "=r"(r[3]) : "r"(addr));
}

__device__ __forceinline__ void mma16816(float* c, const uint32_t* a,
                                         uint32_t b0, uint32_t b1) {
    asm volatile(
        "mma.sync.aligned.m16n8k16.row.col.f32.f16.f16.f32 "
        "{%0,%1,%2,%3}, {%4,%5,%6,%7}, {%8,%9}, {%0,%1,%2,%3};"
        : "+f"(c[0]), "+f"(c[1]), "+f"(c[2]), "+f"(c[3])
        : "r"(a[0]), "r"(a[1]), "r"(a[2]), "r"(a[3]), "r"(b0), "r"(b1));
}

// ---------------- prep kernels ----------------------------------------------

// W int32 -> fp16 (exact). 4 elems/thread.
__global__ void k_convert_w(const int* __restrict__ w) {
    size_t i = ((size_t)blockIdx.x * blockDim.x + threadIdx.x) * 4;
    int4 v = *reinterpret_cast<const int4*>(w + i);
    __half2* dst = reinterpret_cast<__half2*>(g_wh + i);
    dst[0] = __halves2half2(__float2half_rn((float)v.x), __float2half_rn((float)v.y));
    dst[1] = __halves2half2(__float2half_rn((float)v.z), __float2half_rn((float)v.w));
}

// x fp32 -> fp16 raw. 4 elems/thread.
__global__ void k_convert_x(const float* __restrict__ x) {
    size_t i = ((size_t)blockIdx.x * blockDim.x + threadIdx.x) * 4;
    float4 v = *reinterpret_cast<const float4*>(x + i);
    __half2* dst = reinterpret_cast<__half2*>(g_xh + i);
    dst[0] = __halves2half2(__float2half_rn(v.x), __float2half_rn(v.y));
    dst[1] = __halves2half2(__float2half_rn(v.z), __float2half_rn(v.w));
}

// t2a[m][r] = fp16(2 * sum_k x[m][k]*A[r][k]) for r<16, 0 for r in [16,64),
// PLUS fused bb[n][r] = fp16(B[n][r]) padding (256 elems per block).
__global__ __launch_bounds__(256) void k_lora_t(const float* __restrict__ x,
                                                const float* __restrict__ A,
                                                const float* __restrict__ B) {
    __shared__ float sA[16 * 512];
    __shared__ float sT[8][16];
    const int tid = threadIdx.x;
    const int w = tid >> 5, l = tid & 31;
    const int m = blockIdx.x * 8 + w;

    // fused bb fill: 1024 blocks x 256 threads covers 4096*64
    {
        int i = blockIdx.x * 256 + tid;
        int n = i >> 6, r = i & 63;
        float v = (r < 16) ? B[n * 16 + r] : 0.f;
        g_bb[i] = __float2half_rn(v);
    }

    float acc[16];
#pragma unroll
    for (int r = 0; r < 16; r++) acc[r] = 0.f;

    for (int kc = 0; kc < 8; kc++) {
        __syncthreads();
#pragma unroll
        for (int i = 0; i < 8; i++) {
            int v = tid + 256 * i;
            int r = v >> 7, c4 = v & 127;
            *reinterpret_cast<float4*>(&sA[r * 512 + c4 * 4]) =
                *reinterpret_cast<const float4*>(A + (size_t)r * KDIM + kc * 512 + c4 * 4);
        }
        __syncthreads();
#pragma unroll
        for (int i = 0; i < 16; i++) {
            int k = l + i * 32;
            float xv = x[(size_t)m * KDIM + kc * 512 + k];
#pragma unroll
            for (int r = 0; r < 16; r++) acc[r] += xv * sA[r * 512 + k];
        }
    }
#pragma unroll
    for (int r = 0; r < 16; r++) {
        float v = acc[r];
#pragma unroll
        for (int off = 16; off; off >>= 1) v += __shfl_xor_sync(0xffffffffu, v, off);
        acc[r] = v;
    }
    if (l == 0) {
#pragma unroll
        for (int r = 0; r < 16; r++) sT[w][r] = acc[r];
    }
    __syncwarp();
    float tv = (l < 16) ? sT[w][l] : 0.f;
    g_t2a[(size_t)m * 64 + l]      = __float2half_rn(2.0f * tv);
    g_t2a[(size_t)m * 64 + 32 + l] = __float2half_rn(0.f);
}

// ---------------- main HMMA GEMM ---------------------------------------------

__global__ __launch_bounds__(256, 2) void k_gemm(float* __restrict__ out,
                                                 const float* __restrict__ wsp) {
    extern __shared__ char smem_raw[];
    const uint32_t sb = (smem_u32(smem_raw) + 1023u) & ~1023u;  // 1024-aligned
    const int tid = threadIdx.x;
    const int wid = tid >> 5;
    const int lid = tid & 31;
    const int wm = wid & 3;    // 4 warps along M (32 rows each)
    const int wn = wid >> 2;   // 2 warps along N (64 cols each)

    // supertile: 256 bids per group = 8 M x 32 N (full N sweep, 1 MB rows hot)
    const int bid = blockIdx.x;
    const int grp = bid >> 8, loc = bid & 255;
    const int m0 = (grp * 8 + (loc & 7)) * TBM;
    const int n0 = (loc >> 3) * TBN;

    const float ws = wsp[0];

    float acc[2][8][4];
#pragma unroll
    for (int i = 0; i < 2; i++)
#pragma unroll
        for (int j = 0; j < 8; j++)
#pragma unroll
            for (int t = 0; t < 4; t++) acc[i][j][t] = 0.f;

    // cooperative swizzled loader: A 16K + B 16K per chunk, 256 threads
    auto load_chunk = [&](int k) {
        const uint32_t slot = sb + (uint32_t)(k % NSTAGE) * STAGE_BYTES;
        const __half* srcA = g_xh + (size_t)m0 * KDIM + (size_t)k * TBK;
        const __half* srcB = g_wh + (size_t)n0 * KDIM + (size_t)k * TBK;
#pragma unroll
        for (int i = 0; i < 4; i++) {                   // A tile: 1024 x 16B
            int c = tid + 256 * i;
            int row = c >> 3, c16 = c & 7;
            uint32_t so = SWZ128((uint32_t)(row * 128 + c16 * 16));
            cpa16(slot + OFF_A + so, srcA + (size_t)row * KDIM + c16 * 8);
        }
#pragma unroll
        for (int i = 0; i < 4; i++) {                   // B tile: 1024 x 16B
            int c = tid + 256 * i;
            int row = c >> 3, c16 = c & 7;
            uint32_t so = SWZ128((uint32_t)(row * 128 + c16 * 16));
            cpa16(slot + OFF_B + so, srcB + (size_t)row * KDIM + c16 * 8);
        }
    };

    load_chunk(0); cpa_commit();
    load_chunk(1); cpa_commit();

    // per-lane ldmatrix addressing constants
    const uint32_t lrow = (uint32_t)(lid & 15);        // row within 16-row tile
    const uint32_t lcol = (uint32_t)((lid >> 4) * 16); // 0 or 16 bytes (k half)
    const uint32_t swz  = ((lrow & 7u) << 4);

    for (int k = 0; k < NKC; k++) {
        if (k + 2 < NKC) load_chunk(k + 2);
        cpa_commit();                      // keep group count uniform
        cpa_wait<2>();                     // stage k resident (this thread)
        __syncthreads();                   // publish to all threads

        const uint32_t slot = sb + (uint32_t)(k % NSTAGE) * STAGE_BYTES;
        const uint32_t aBase = slot + OFF_A + (uint32_t)(wm * 32) * 128 + lrow * 128;
        const uint32_t bBase = slot + OFF_B + (uint32_t)(wn * 64) * 128 + lrow * 128;

#pragma unroll
        for (int ks = 0; ks < 4; ks++) {
            const uint32_t csw = ((uint32_t)(ks * 32) + lcol) ^ swz;

            uint32_t bfr[4][4];
#pragma unroll
            for (int ntp = 0; ntp < 4; ntp++)
                ldsm_x4(bfr[ntp], bBase + (uint32_t)(ntp * 16) * 128 + csw);

            uint32_t af[2][4];
#pragma unroll
            for (int mt = 0; mt < 2; mt++)
                ldsm_x4(af[mt], aBase + (uint32_t)(mt * 16) * 128 + csw);
#pragma unroll
            for (int mt = 0; mt < 2; mt++)
#pragma unroll
                for (int nt = 0; nt < 8; nt++)
                    mma16816(acc[mt][nt], af[mt],
                             bfr[nt >> 1][nt & 1], bfr[nt >> 1][2 + (nt & 1)]);
        }
        __syncthreads();                   // done reading slot before overwrite
    }

    // ---------- epilogue: scale by ws, add LoRA via one fp16 MMA chunk -------
    // A' = t2a[m0..m0+128) (16 KB), B' = bb[n0..n0+128) (16 KB), 128B rows.
    {
        const char* tA = reinterpret_cast<const char*>(g_t2a) + (size_t)m0 * 128;
        const char* tB = reinterpret_cast<const char*>(g_bb)  + (size_t)n0 * 128;
#pragma unroll
        for (int i = 0; i < 4; i++) {
            int c = tid + 256 * i;
            int row = c >> 3, c16 = c & 7;
            uint32_t so = SWZ128((uint32_t)(row * 128 + c16 * 16));
            cpa16(sb + OFF_A + so, tA + (size_t)row * 128 + c16 * 16);
            cpa16(sb + OFF_B + so, tB + (size_t)row * 128 + c16 * 16);
        }
        cpa_commit();
        cpa_wait<0>();
        __syncthreads();
    }

    // scale base accumulators
#pragma unroll
    for (int mt = 0; mt < 2; mt++)
#pragma unroll
        for (int nt = 0; nt < 8; nt++)
#pragma unroll
            for (int e = 0; e < 4; e++) acc[mt][nt][e] *= ws;

    // LoRA fp16 MMA (ks=0 slice carries the 16 real rank columns; rest zero)
    {
        const uint32_t csw0 = lcol ^ swz;
        const uint32_t aB = sb + OFF_A + (uint32_t)(wm * 32) * 128 + lrow * 128;
        const uint32_t bB = sb + OFF_B + (uint32_t)(wn * 64) * 128 + lrow * 128;
        uint32_t bl[4][4];
#pragma unroll
        for (int ntp = 0; ntp < 4; ntp++)
            ldsm_x4(bl[ntp], bB + (uint32_t)(ntp * 16) * 128 + csw0);
        uint32_t al[2][4];
#pragma unroll
        for (int mt = 0; mt < 2; mt++)
            ldsm_x4(al[mt], aB + (uint32_t)(mt * 16) * 128 + csw0);
#pragma unroll
        for (int mt = 0; mt < 2; mt++)
#pragma unroll
            for (int nt = 0; nt < 8; nt++)
                mma16816(acc[mt][nt], al[mt],
                         bl[nt >> 1][nt & 1], bl[nt >> 1][2 + (nt & 1)]);
    }

    // store (float2 per lane, 32B-sector aligned)
    const int rBase = m0 + wm * 32 + (lid >> 2);
    const int cBase = n0 + wn * 64 + (lid & 3) * 2;
#pragma unroll
    for (int mt = 0; mt < 2; mt++) {
#pragma unroll
        for (int nt = 0; nt < 8; nt++) {
            float* p0 = out + (size_t)(rBase + mt * 16) * NDIM + cBase + nt * 8;
            float* p1 = out + (size_t)(rBase + mt * 16 + 8) * NDIM + cBase + nt * 8;
            *reinterpret_cast<float2*>(p0) = make_float2(acc[mt][nt][0], acc[mt][nt][1]);
            *reinterpret_cast<float2*>(p1) = make_float2(acc[mt][nt][2], acc[mt][nt][3]);
        }
    }
}

// ---------------- launch -----------------------------------------------------

extern "C" void kernel_launch(void* const* d_in, const int* in_sizes, int n_in,
                              void* d_out, int out_size) {
    (void)in_sizes; (void)n_in; (void)out_size;
    const float* x  = (const float*)d_in[0];
    const int*   wi = (const int*)d_in[1];
    const float* ws = (const float*)d_in[2];
    const float* lA = (const float*)d_in[3];
    const float* lB = (const float*)d_in[4];
    float* out = (float*)d_out;

    cudaFuncSetAttribute(k_gemm, cudaFuncAttributeMaxDynamicSharedMemorySize, SMEM_ALLOC);

    k_convert_w<<<(NDIM * (size_t)KDIM) / (256 * 4), 256>>>(wi);
    k_convert_x<<<(MDIM * (size_t)KDIM) / (256 * 4), 256>>>(x);
    k_lora_t   <<<MDIM / 8, 256>>>(x, lA, lB);          // bb fill fused in
    k_gemm     <<<(MDIM / TBM) * (NDIM / TBN), 256, SMEM_ALLOC>>>(out, ws);
}